// round 1
// baseline (speedup 1.0000x reference)
#include <cuda_runtime.h>
#include <math.h>

#define BB 16
#define CC 64
#define HH 144
#define WW 144
#define G9 9
#define C9 576
#define NPIX 2304            // 48*48
#define NBHW 36864.0f        // 16*48*48
#define EPSV 1e-5f

// ---------------- scratch (device globals; no allocations allowed) ----------------
__device__ float d_pool[BB*G9*CC*NPIX];   // [b][g][i][y][x] focus layout, 84.9MB
__device__ float d_xmix[BB*C9*NPIX];      // mixed (pre-BN), 84.9MB
__device__ float d_conv[BB*CC*NPIX];      // dwconv sum (pre-BN), 9.4MB
__device__ float d_sum1[C9];
__device__ float d_sq1[C9];
__device__ float d_sum2[CC];
__device__ float d_sq2[CC];
__device__ float d_sc1[C9];
__device__ float d_sh1[C9];
__device__ float d_sc2[CC];
__device__ float d_sh2[CC];
__device__ float d_ck[CC*169];            // combined 13x13 depthwise kernel per channel

// ---------------- K0: zero stats (graph replays must be idempotent) ----------------
__global__ void kz() {
    int t = blockIdx.x * 256 + threadIdx.x;
    if (t < C9) { d_sum1[t] = 0.f; d_sq1[t] = 0.f; }
    if (t < CC) { d_sum2[t] = 0.f; d_sq2[t] = 0.f; }
}

// ---------------- K1: maxpool3x3 (stride1,pad1) + focus downsample ----------------
// block: (y, i, b) with 144 threads; computes pooled rows 3y..3y+2, scatters into
// focus layout d_pool[b][g=di*3+dj][i][y][x].
__global__ void kpool(const float* __restrict__ x) {
    int y = blockIdx.x;   // 0..47
    int i = blockIdx.y;   // 0..63
    int b = blockIdx.z;   // 0..15
    __shared__ float s_in[5][WW];
    __shared__ float s_vm[3][WW];
    int t = threadIdx.x;  // 0..143
    const float* src = x + (size_t)(b * CC + i) * (HH * WW);
#pragma unroll
    for (int k = 0; k < 5; k++) {
        int r = 3 * y - 1 + k;
        r = max(0, min(HH - 1, r));     // clamp == -inf pad for max
        s_in[k][t] = src[r * WW + t];
    }
    __syncthreads();
#pragma unroll
    for (int di = 0; di < 3; di++)
        s_vm[di][t] = fmaxf(fmaxf(s_in[di][t], s_in[di + 1][t]), s_in[di + 2][t]);
    __syncthreads();
    int xm1 = max(t - 1, 0), xp1 = min(t + 1, WW - 1);
    int dj = t % 3, xq = t / 3;
    float* dst = d_pool + ((size_t)(b * G9) * CC + i) * NPIX + y * 48 + xq;
#pragma unroll
    for (int di = 0; di < 3; di++) {
        float m = fmaxf(fmaxf(s_vm[di][xm1], s_vm[di][t]), s_vm[di][xp1]);
        dst[(size_t)(di * 3 + dj) * (CC * NPIX)] = m;
    }
}

// ---------------- K2: group channel mixer (9x: 64x64 x 36864 GEMM) + BN1 stats ----
// block = (b,g,pixel-tile of 256). 256 threads, 8 ch x 8 px register tile.
__global__ void kmix(const float* __restrict__ wm) {
    int bid = blockIdx.x;
    int tile = bid % 9;
    int g = (bid / 9) % 9;
    int b = bid / 81;
    __shared__ float Wt[64 * 64];   // transposed: Wt[i][o]
    __shared__ float Ins[8 * 256];
    int tid = threadIdx.x;
    for (int idx = tid; idx < 4096; idx += 256) {
        int o = idx >> 6, i = idx & 63;
        Wt[i * 64 + o] = wm[g * 4096 + idx];
    }
    float acc[8][8];
#pragma unroll
    for (int a = 0; a < 8; a++)
#pragma unroll
        for (int p = 0; p < 8; p++) acc[a][p] = 0.f;

    const float* inbase = d_pool + (size_t)((b * G9 + g) * CC) * NPIX + tile * 256;
    int lane = tid & 31;
    int warp = tid >> 5;
    int o0 = warp * 8;
    int pA = lane * 4;   // pixels pA..pA+3 and pA+128..pA+131

    for (int k0 = 0; k0 < 64; k0 += 8) {
        __syncthreads();
        {
            const float* s = inbase + (size_t)(k0 + warp) * NPIX;
            float4 a = *(const float4*)(s + lane * 4);
            float4 c = *(const float4*)(s + lane * 4 + 128);
            *(float4*)(&Ins[warp * 256 + lane * 4]) = a;
            *(float4*)(&Ins[warp * 256 + lane * 4 + 128]) = c;
        }
        __syncthreads();
#pragma unroll
        for (int i = 0; i < 8; i++) {
            float4 w0 = *(const float4*)(&Wt[(k0 + i) * 64 + o0]);
            float4 w1 = *(const float4*)(&Wt[(k0 + i) * 64 + o0 + 4]);
            float4 xa = *(const float4*)(&Ins[i * 256 + pA]);
            float4 xb = *(const float4*)(&Ins[i * 256 + pA + 128]);
            float wv[8] = {w0.x, w0.y, w0.z, w0.w, w1.x, w1.y, w1.z, w1.w};
            float xv[8] = {xa.x, xa.y, xa.z, xa.w, xb.x, xb.y, xb.z, xb.w};
#pragma unroll
            for (int oi = 0; oi < 8; oi++)
#pragma unroll
                for (int pj = 0; pj < 8; pj++) acc[oi][pj] = fmaf(wv[oi], xv[pj], acc[oi][pj]);
        }
    }

    float* outbase = d_xmix + (size_t)(b * C9 + g * 64) * NPIX + tile * 256;
#pragma unroll
    for (int oi = 0; oi < 8; oi++) {
        int o = o0 + oi;
        *(float4*)(outbase + (size_t)o * NPIX + pA) =
            make_float4(acc[oi][0], acc[oi][1], acc[oi][2], acc[oi][3]);
        *(float4*)(outbase + (size_t)o * NPIX + pA + 128) =
            make_float4(acc[oi][4], acc[oi][5], acc[oi][6], acc[oi][7]);
        float s = 0.f, q = 0.f;
#pragma unroll
        for (int pj = 0; pj < 8; pj++) { s += acc[oi][pj]; q += acc[oi][pj] * acc[oi][pj]; }
#pragma unroll
        for (int off = 16; off; off >>= 1) {
            s += __shfl_xor_sync(0xffffffffu, s, off);
            q += __shfl_xor_sync(0xffffffffu, q, off);
        }
        if (lane == 0) {
            atomicAdd(&d_sum1[g * 64 + o], s);
            atomicAdd(&d_sq1[g * 64 + o], q);
        }
    }
}

// ---------------- K3: BN1 affine params + combined 13x13 depthwise kernel --------
__global__ void kaff1(const float* __restrict__ gm, const float* __restrict__ bm,
                      const float* __restrict__ wh1, const float* __restrict__ wv1,
                      const float* __restrict__ wh2, const float* __restrict__ wv2) {
    int t = threadIdx.x;
    if (t < C9) {
        float mean = d_sum1[t] / NBHW;
        float var = d_sq1[t] / NBHW - mean * mean;
        float sc = gm[t] * rsqrtf(var + EPSV);
        d_sc1[t] = sc;
        d_sh1[t] = bm[t] - mean * sc;
    }
    if (t < CC) {
        float ck[169];
#pragma unroll
        for (int j = 0; j < 169; j++) ck[j] = 0.f;
        const float* a1 = wh1 + t * 33;  // (11,3): dy=a-5, dx=b-1
#pragma unroll
        for (int a = 0; a < 11; a++)
#pragma unroll
            for (int bq = 0; bq < 3; bq++) ck[(a + 1) * 13 + (bq + 5)] += a1[a * 3 + bq];
        const float* a2 = wv1 + t * 33;  // (3,11): dy=a-1, dx=b-5
#pragma unroll
        for (int a = 0; a < 3; a++)
#pragma unroll
            for (int bq = 0; bq < 11; bq++) ck[(a + 5) * 13 + (bq + 1)] += a2[a * 11 + bq];
        const float* a3 = wh2 + t * 33;  // sheared: dy=a-5, dx=(b-1)-(a-5)
#pragma unroll
        for (int a = 0; a < 11; a++)
#pragma unroll
            for (int bq = 0; bq < 3; bq++) ck[(a + 1) * 13 + (bq + 10 - a)] += a3[a * 3 + bq];
        const float* a4 = wv2 + t * 33;  // sheared: dy=(a-1)-(b-5), dx=b-5
#pragma unroll
        for (int a = 0; a < 3; a++)
#pragma unroll
            for (int bq = 0; bq < 11; bq++) ck[(a - bq + 10) * 13 + (bq + 1)] += a4[a * 11 + bq];
#pragma unroll
        for (int j = 0; j < 169; j++) d_ck[t * 169 + j] = ck[j];
    }
}

// ---------------- K4: 13x13 depthwise conv on BN1(x_tem) + BN2 stats --------------
// block per (b,c). smem tile 60x60 (stride 64), 288 threads = 48 rows x 6 strips of 8px.
__global__ void kdw() {
    int c = blockIdx.x & 63;
    int b = blockIdx.x >> 6;
    __shared__ float T[60 * 64];
    __shared__ float ckw[169];
    __shared__ float red[2][9];
    int tid = threadIdx.x;  // 0..287
    float sc = d_sc1[c], sh = d_sh1[c];
    const float* src = d_xmix + (size_t)(b * C9 + c) * NPIX;
    for (int idx = tid; idx < 3600; idx += 288) {
        int row = idx / 60, col = idx - row * 60;
        int gy = row - 6, gx = col - 6;
        float v = 0.f;
        if (gy >= 0 && gy < 48 && gx >= 0 && gx < 48) v = src[gy * 48 + gx] * sc + sh;
        T[row * 64 + col] = v;
    }
    for (int idx = tid; idx < 169; idx += 288) ckw[idx] = d_ck[c * 169 + idx];
    __syncthreads();

    int y = tid / 6;
    int x0 = (tid - y * 6) * 8;
    float acc[8];
#pragma unroll
    for (int p = 0; p < 8; p++) acc[p] = 0.f;
#pragma unroll
    for (int dy = 0; dy < 13; dy++) {
        const float* row = &T[(y + dy) * 64 + x0];
        float v[20];
#pragma unroll
        for (int q = 0; q < 5; q++) {
            float4 f = *(const float4*)(row + q * 4);
            v[q * 4 + 0] = f.x; v[q * 4 + 1] = f.y; v[q * 4 + 2] = f.z; v[q * 4 + 3] = f.w;
        }
#pragma unroll
        for (int dx = 0; dx < 13; dx++) {
            float wv = ckw[dy * 13 + dx];
#pragma unroll
            for (int p = 0; p < 8; p++) acc[p] = fmaf(wv, v[p + dx], acc[p]);
        }
    }
    float* dst = d_conv + (size_t)(b * CC + c) * NPIX + y * 48 + x0;
    *(float4*)(dst) = make_float4(acc[0], acc[1], acc[2], acc[3]);
    *(float4*)(dst + 4) = make_float4(acc[4], acc[5], acc[6], acc[7]);

    float s = 0.f, q = 0.f;
#pragma unroll
    for (int p = 0; p < 8; p++) { s += acc[p]; q += acc[p] * acc[p]; }
#pragma unroll
    for (int off = 16; off; off >>= 1) {
        s += __shfl_xor_sync(0xffffffffu, s, off);
        q += __shfl_xor_sync(0xffffffffu, q, off);
    }
    int wid = tid >> 5, lane = tid & 31;
    if (lane == 0) { red[0][wid] = s; red[1][wid] = q; }
    __syncthreads();
    if (tid == 0) {
        float ss = 0.f, qq = 0.f;
#pragma unroll
        for (int wq = 0; wq < 9; wq++) { ss += red[0][wq]; qq += red[1][wq]; }
        atomicAdd(&d_sum2[c], ss);
        atomicAdd(&d_sq2[c], qq);
    }
}

// ---------------- K5: BN2 affine params --------------------------------------------
__global__ void kaff2(const float* __restrict__ gn, const float* __restrict__ bn) {
    int t = threadIdx.x;
    float mean = d_sum2[t] / NBHW;
    float var = d_sq2[t] / NBHW - mean * mean;
    float sc = gn[t] * rsqrtf(var + EPSV);
    d_sc2[t] = sc;
    d_sh2[t] = bn[t] - mean * sc;
}

// ---------------- K6: pixel-shuffle gather + sigmoid gate --------------------------
__global__ void kfinal(const float* __restrict__ x, float* __restrict__ out) {
    int idx = blockIdx.x * 256 + threadIdx.x;   // one 4-pixel group
    int Xg = idx % 36;
    int rest = idx / 36;
    int Y = rest % 144;
    rest /= 144;
    int c = rest & 63;
    int b = rest >> 6;
    size_t base = ((size_t)(b * CC + c) * HH + Y) * WW + Xg * 4;
    float4 xv = *(const float4*)(x + base);
    const float* xp = (const float*)&xv;
    int y = Y / 3;
    int ry = Y - 3 * y;
    float o[4];
#pragma unroll
    for (int l = 0; l < 4; l++) {
        int X = Xg * 4 + l;
        int xq = X / 3;
        int rx = X - 3 * xq;
        int m = c * 9 + ry * 3 + rx;
        float v;
        if (m < 64)
            v = d_conv[(size_t)(b * CC + m) * NPIX + y * 48 + xq] * d_sc2[m] + d_sh2[m];
        else
            v = d_xmix[(size_t)(b * C9 + m) * NPIX + y * 48 + xq] * d_sc1[m] + d_sh1[m];
        float sg = 1.f / (1.f + __expf(-v));
        o[l] = xp[l] * sg;
    }
    *(float4*)(out + base) = make_float4(o[0], o[1], o[2], o[3]);
}

// ---------------- launch -----------------------------------------------------------
extern "C" void kernel_launch(void* const* d_in, const int* in_sizes, int n_in,
                              void* d_out, int out_size) {
    const float* x   = (const float*)d_in[0];
    const float* wm  = (const float*)d_in[1];
    const float* gm  = (const float*)d_in[2];
    const float* bm  = (const float*)d_in[3];
    const float* wh1 = (const float*)d_in[4];
    const float* wv1 = (const float*)d_in[5];
    const float* wh2 = (const float*)d_in[6];
    const float* wv2 = (const float*)d_in[7];
    const float* gn  = (const float*)d_in[8];
    const float* bn  = (const float*)d_in[9];
    float* out = (float*)d_out;

    kz<<<3, 256>>>();
    kpool<<<dim3(48, 64, 16), 144>>>(x);
    kmix<<<1296, 256>>>(wm);
    kaff1<<<1, 576>>>(gm, bm, wh1, wv1, wh2, wv2);
    kdw<<<1024, 288>>>();
    kaff2<<<1, 64>>>(gn, bn);
    kfinal<<<20736, 256>>>(x, out);
}

// round 4
// speedup vs baseline: 1.1056x; 1.1056x over previous
#include <cuda_runtime.h>
#include <math.h>

#define BB 16
#define CC 64
#define HH 144
#define WW 144
#define G9 9
#define C9 576
#define NPIX 2304            // 48*48
#define NBHW 36864.0f        // 16*48*48
#define EPSV 1e-5f

typedef unsigned long long u64;

// ---- packed f32x2 helpers (FFMA2 path: only reachable via PTX) ----
__device__ __forceinline__ u64 pk2(float v) {
    u64 r; asm("mov.b64 %0,{%1,%1};" : "=l"(r) : "f"(v)); return r;
}
__device__ __forceinline__ u64 pk(float lo, float hi) {
    u64 r; asm("mov.b64 %0,{%1,%2};" : "=l"(r) : "f"(lo), "f"(hi)); return r;
}
__device__ __forceinline__ u64 f2fma(u64 a, u64 b, u64 c) {
    u64 d; asm("fma.rn.f32x2 %0,%1,%2,%3;" : "=l"(d) : "l"(a), "l"(b), "l"(c)); return d;
}
__device__ __forceinline__ u64 f2add(u64 a, u64 b) {
    u64 d; asm("add.rn.f32x2 %0,%1,%2;" : "=l"(d) : "l"(a), "l"(b)); return d;
}
__device__ __forceinline__ void unpk(u64 v, float& lo, float& hi) {
    asm("mov.b64 {%0,%1},%2;" : "=f"(lo), "=f"(hi) : "l"(v));
}

// ---------------- scratch (device globals; no allocations allowed) ----------------
__device__ float d_pool[BB*G9*CC*NPIX];   // [b][g][i][y][x] focus layout
__device__ float d_xmix[BB*C9*NPIX];      // mixed (pre-BN)
__device__ float d_conv[BB*CC*NPIX];      // dwconv sum (pre-BN)
__device__ float d_sum1[C9];
__device__ float d_sq1[C9];
__device__ float d_sum2[CC];
__device__ float d_sq2[CC];
__device__ float d_sc1[C9];
__device__ float d_sh1[C9];
__device__ float d_sc2[CC];
__device__ float d_sh2[CC];
__device__ float d_ck[CC*169];            // combined 13x13 depthwise kernel per channel

// ---------------- K1: maxpool3x3 (stride1,pad1) + focus downsample ----------------
// block: (y, i, b) with 144 threads; block (0,0,0) also zeroes the BN stat buffers
// (safe: kmix/kdw consume them only in later launches).
__global__ void kpool(const float* __restrict__ x) {
    int y = blockIdx.x;   // 0..47
    int i = blockIdx.y;   // 0..63
    int b = blockIdx.z;   // 0..15
    __shared__ float s_in[5][WW];
    __shared__ float s_vm[3][WW];
    int t = threadIdx.x;  // 0..143
    if (blockIdx.x == 0 && blockIdx.y == 0 && blockIdx.z == 0) {
        for (int j = t; j < C9; j += 144) { d_sum1[j] = 0.f; d_sq1[j] = 0.f; }
        for (int j = t; j < CC; j += 144) { d_sum2[j] = 0.f; d_sq2[j] = 0.f; }
    }
    const float* src = x + (size_t)(b * CC + i) * (HH * WW);
#pragma unroll
    for (int k = 0; k < 5; k++) {
        int r = 3 * y - 1 + k;
        r = max(0, min(HH - 1, r));     // clamp == -inf pad for max
        s_in[k][t] = src[r * WW + t];
    }
    __syncthreads();
#pragma unroll
    for (int di = 0; di < 3; di++)
        s_vm[di][t] = fmaxf(fmaxf(s_in[di][t], s_in[di + 1][t]), s_in[di + 2][t]);
    __syncthreads();
    int xm1 = max(t - 1, 0), xp1 = min(t + 1, WW - 1);
    int dj = t % 3, xq = t / 3;
    float* dst = d_pool + ((size_t)(b * G9) * CC + i) * NPIX + y * 48 + xq;
#pragma unroll
    for (int di = 0; di < 3; di++) {
        float m = fmaxf(fmaxf(s_vm[di][xm1], s_vm[di][t]), s_vm[di][xp1]);
        dst[(size_t)(di * 3 + dj) * (CC * NPIX)] = m;
    }
}

// ---------------- K2: group channel mixer (9x: 64x64 x 36864 GEMM) + BN1 stats ----
// block = (b,g,pixel-tile of 256). 256 threads, 8 ch x 8 px register tile, FFMA2.
__global__ void __launch_bounds__(256) kmix(const float* __restrict__ wm) {
    int bid = blockIdx.x;
    int tile = bid % 9;
    int g = (bid / 9) % 9;
    int b = bid / 81;
    __shared__ __align__(16) float Wt[64 * 64];   // transposed: Wt[i][o]
    __shared__ __align__(16) float Ins[8 * 256];
    int tid = threadIdx.x;
    for (int idx = tid; idx < 4096; idx += 256) {
        int o = idx >> 6, i = idx & 63;
        Wt[i * 64 + o] = wm[g * 4096 + idx];
    }
    u64 acc2[8][4];
#pragma unroll
    for (int a = 0; a < 8; a++)
#pragma unroll
        for (int p = 0; p < 4; p++) acc2[a][p] = 0ull;

    const float* inbase = d_pool + (size_t)((b * G9 + g) * CC) * NPIX + tile * 256;
    int lane = tid & 31;
    int warp = tid >> 5;
    int o0 = warp * 8;
    int pA = lane * 4;   // pixels pA..pA+3 and pA+128..pA+131

    for (int k0 = 0; k0 < 64; k0 += 8) {
        __syncthreads();
        {
            const float* s = inbase + (size_t)(k0 + warp) * NPIX;
            float4 a = *(const float4*)(s + lane * 4);
            float4 c = *(const float4*)(s + lane * 4 + 128);
            *(float4*)(&Ins[warp * 256 + lane * 4]) = a;
            *(float4*)(&Ins[warp * 256 + lane * 4 + 128]) = c;
        }
        __syncthreads();
#pragma unroll
        for (int i = 0; i < 8; i++) {
            float4 w0 = *(const float4*)(&Wt[(k0 + i) * 64 + o0]);
            float4 w1 = *(const float4*)(&Wt[(k0 + i) * 64 + o0 + 4]);
            u64 wp[8];
            wp[0] = pk2(w0.x); wp[1] = pk2(w0.y); wp[2] = pk2(w0.z); wp[3] = pk2(w0.w);
            wp[4] = pk2(w1.x); wp[5] = pk2(w1.y); wp[6] = pk2(w1.z); wp[7] = pk2(w1.w);
            ulonglong2 xa = *(const ulonglong2*)(&Ins[i * 256 + pA]);
            ulonglong2 xb = *(const ulonglong2*)(&Ins[i * 256 + pA + 128]);
#pragma unroll
            for (int oi = 0; oi < 8; oi++) {
                acc2[oi][0] = f2fma(wp[oi], xa.x, acc2[oi][0]);
                acc2[oi][1] = f2fma(wp[oi], xa.y, acc2[oi][1]);
                acc2[oi][2] = f2fma(wp[oi], xb.x, acc2[oi][2]);
                acc2[oi][3] = f2fma(wp[oi], xb.y, acc2[oi][3]);
            }
        }
    }

    float* outbase = d_xmix + (size_t)(b * C9 + g * 64) * NPIX + tile * 256;
#pragma unroll
    for (int oi = 0; oi < 8; oi++) {
        int o = o0 + oi;
        ulonglong2 st0; st0.x = acc2[oi][0]; st0.y = acc2[oi][1];
        ulonglong2 st1; st1.x = acc2[oi][2]; st1.y = acc2[oi][3];
        *(ulonglong2*)(outbase + (size_t)o * NPIX + pA) = st0;
        *(ulonglong2*)(outbase + (size_t)o * NPIX + pA + 128) = st1;
        u64 s2 = f2add(f2add(acc2[oi][0], acc2[oi][1]), f2add(acc2[oi][2], acc2[oi][3]));
        u64 q2 = 0ull;
#pragma unroll
        for (int p = 0; p < 4; p++) q2 = f2fma(acc2[oi][p], acc2[oi][p], q2);
        float sl, sh_, ql, qh;
        unpk(s2, sl, sh_); unpk(q2, ql, qh);
        float s = sl + sh_, q = ql + qh;
#pragma unroll
        for (int off = 16; off; off >>= 1) {
            s += __shfl_xor_sync(0xffffffffu, s, off);
            q += __shfl_xor_sync(0xffffffffu, q, off);
        }
        if (lane == 0) {
            atomicAdd(&d_sum1[g * 64 + o], s);
            atomicAdd(&d_sq1[g * 64 + o], q);
        }
    }
}

// ---------------- K3: BN1 affine params + combined 13x13 depthwise kernel --------
// grid 65: blocks 0..63 build d_ck[c] (one thread per tap); block 64 does BN1 stats.
__global__ void kaff1(const float* __restrict__ gm, const float* __restrict__ bm,
                      const float* __restrict__ wh1, const float* __restrict__ wv1,
                      const float* __restrict__ wh2, const float* __restrict__ wv2) {
    int t = threadIdx.x;
    if (blockIdx.x == 64) {
        if (t < C9) {
            float mean = d_sum1[t] / NBHW;
            float var = d_sq1[t] / NBHW - mean * mean;
            float sc = gm[t] * rsqrtf(var + EPSV);
            d_sc1[t] = sc;
            d_sh1[t] = bm[t] - mean * sc;
        }
        return;
    }
    int c = blockIdx.x;
    if (t >= 169) return;
    int dy = t / 13, dx = t - dy * 13;
    float v = 0.f;
    // a1 (11,3): dy=a+1, dx=b+5
    { int a = dy - 1, bq = dx - 5;
      if (a >= 0 && a < 11 && bq >= 0 && bq < 3) v += wh1[c * 33 + a * 3 + bq]; }
    // a2 (3,11): dy=a+5, dx=b+1
    { int a = dy - 5, bq = dx - 1;
      if (a >= 0 && a < 3 && bq >= 0 && bq < 11) v += wv1[c * 33 + a * 11 + bq]; }
    // a3 sheared (11,3): dy=a+1, dx=b+10-a -> b=dx+dy-11
    { int a = dy - 1, bq = dx + dy - 11;
      if (a >= 0 && a < 11 && bq >= 0 && bq < 3) v += wh2[c * 33 + a * 3 + bq]; }
    // a4 sheared (3,11): dx=b+1, dy=a-b+10 -> a=dy+dx-11
    { int a = dy + dx - 11, bq = dx - 1;
      if (a >= 0 && a < 3 && bq >= 0 && bq < 11) v += wv2[c * 33 + a * 11 + bq]; }
    d_ck[c * 169 + t] = v;
}

// ---------------- K4: 13x13 depthwise conv on BN1(x_tem) + BN2 stats (FFMA2) ------
__global__ void __launch_bounds__(288) kdw() {
    int c = blockIdx.x & 63;
    int b = blockIdx.x >> 6;
    __shared__ __align__(16) float T[60 * 64];
    __shared__ float ckw[169];
    __shared__ float red[2][9];
    int tid = threadIdx.x;  // 0..287
    float sc = d_sc1[c], sh = d_sh1[c];
    const float* src = d_xmix + (size_t)(b * C9 + c) * NPIX;
    for (int idx = tid; idx < 3600; idx += 288) {
        int row = idx / 60, col = idx - row * 60;
        int gy = row - 6, gx = col - 6;
        float v = 0.f;
        if (gy >= 0 && gy < 48 && gx >= 0 && gx < 48) v = src[gy * 48 + gx] * sc + sh;
        T[row * 64 + col] = v;
    }
    for (int idx = tid; idx < 169; idx += 288) ckw[idx] = d_ck[c * 169 + idx];
    __syncthreads();

    int y = tid / 6;
    int x0 = (tid - y * 6) * 8;
    u64 acc2[4] = {0ull, 0ull, 0ull, 0ull};
#pragma unroll
    for (int dy = 0; dy < 13; dy++) {
        const float* row = &T[(y + dy) * 64 + x0];
        float f[20];
#pragma unroll
        for (int q = 0; q < 5; q++) {
            float4 fq = *(const float4*)(row + q * 4);
            f[q * 4 + 0] = fq.x; f[q * 4 + 1] = fq.y; f[q * 4 + 2] = fq.z; f[q * 4 + 3] = fq.w;
        }
        u64 pv0[10], pv1[9];
#pragma unroll
        for (int k = 0; k < 10; k++) pv0[k] = pk(f[2 * k], f[2 * k + 1]);
#pragma unroll
        for (int k = 0; k < 9; k++) pv1[k] = pk(f[2 * k + 1], f[2 * k + 2]);
#pragma unroll
        for (int dx = 0; dx < 13; dx++) {
            u64 wp = pk2(ckw[dy * 13 + dx]);
            if ((dx & 1) == 0) {
                int h = dx >> 1;
#pragma unroll
                for (int j = 0; j < 4; j++) acc2[j] = f2fma(wp, pv0[j + h], acc2[j]);
            } else {
                int h = dx >> 1;
#pragma unroll
                for (int j = 0; j < 4; j++) acc2[j] = f2fma(wp, pv1[j + h], acc2[j]);
            }
        }
    }
    float* dst = d_conv + (size_t)(b * CC + c) * NPIX + y * 48 + x0;
    ulonglong2 st0; st0.x = acc2[0]; st0.y = acc2[1];
    ulonglong2 st1; st1.x = acc2[2]; st1.y = acc2[3];
    *(ulonglong2*)(dst) = st0;
    *(ulonglong2*)(dst + 4) = st1;

    u64 s2 = f2add(f2add(acc2[0], acc2[1]), f2add(acc2[2], acc2[3]));
    u64 q2 = 0ull;
#pragma unroll
    for (int j = 0; j < 4; j++) q2 = f2fma(acc2[j], acc2[j], q2);
    float sl, sh_, ql, qh;
    unpk(s2, sl, sh_); unpk(q2, ql, qh);
    float s = sl + sh_, q = ql + qh;
#pragma unroll
    for (int off = 16; off; off >>= 1) {
        s += __shfl_xor_sync(0xffffffffu, s, off);
        q += __shfl_xor_sync(0xffffffffu, q, off);
    }
    int wid = tid >> 5, lane = tid & 31;
    if (lane == 0) { red[0][wid] = s; red[1][wid] = q; }
    __syncthreads();
    if (tid == 0) {
        float ss = 0.f, qq = 0.f;
#pragma unroll
        for (int wq = 0; wq < 9; wq++) { ss += red[0][wq]; qq += red[1][wq]; }
        atomicAdd(&d_sum2[c], ss);
        atomicAdd(&d_sq2[c], qq);
    }
}

// ---------------- K5: BN2 affine params --------------------------------------------
__global__ void kaff2(const float* __restrict__ gn, const float* __restrict__ bn) {
    int t = threadIdx.x;
    float mean = d_sum2[t] / NBHW;
    float var = d_sq2[t] / NBHW - mean * mean;
    float sc = gn[t] * rsqrtf(var + EPSV);
    d_sc2[t] = sc;
    d_sh2[t] = bn[t] - mean * sc;
}

// ---------------- K6: pixel-shuffle gather + sigmoid gate --------------------------
__global__ void kfinal(const float* __restrict__ x, float* __restrict__ out) {
    int idx = blockIdx.x * 256 + threadIdx.x;   // one 4-pixel group
    int Xg = idx % 36;
    int rest = idx / 36;
    int Y = rest % 144;
    rest /= 144;
    int c = rest & 63;
    int b = rest >> 6;
    size_t base = ((size_t)(b * CC + c) * HH + Y) * WW + Xg * 4;
    float4 xv = *(const float4*)(x + base);
    const float* xp = (const float*)&xv;
    int y = Y / 3;
    int ry = Y - 3 * y;
    float o[4];
#pragma unroll
    for (int l = 0; l < 4; l++) {
        int X = Xg * 4 + l;
        int xq = X / 3;
        int rx = X - 3 * xq;
        int m = c * 9 + ry * 3 + rx;
        float v;
        if (m < 64)
            v = d_conv[(size_t)(b * CC + m) * NPIX + y * 48 + xq] * d_sc2[m] + d_sh2[m];
        else
            v = d_xmix[(size_t)(b * C9 + m) * NPIX + y * 48 + xq] * d_sc1[m] + d_sh1[m];
        float sg = 1.f / (1.f + __expf(-v));
        o[l] = xp[l] * sg;
    }
    *(float4*)(out + base) = make_float4(o[0], o[1], o[2], o[3]);
}

// ---------------- launch -----------------------------------------------------------
extern "C" void kernel_launch(void* const* d_in, const int* in_sizes, int n_in,
                              void* d_out, int out_size) {
    const float* x   = (const float*)d_in[0];
    const float* wm  = (const float*)d_in[1];
    const float* gm  = (const float*)d_in[2];
    const float* bm  = (const float*)d_in[3];
    const float* wh1 = (const float*)d_in[4];
    const float* wv1 = (const float*)d_in[5];
    const float* wh2 = (const float*)d_in[6];
    const float* wv2 = (const float*)d_in[7];
    const float* gn  = (const float*)d_in[8];
    const float* bn  = (const float*)d_in[9];
    float* out = (float*)d_out;

    kpool<<<dim3(48, 64, 16), 144>>>(x);
    kmix<<<1296, 256>>>(wm);
    kaff1<<<65, 576>>>(gm, bm, wh1, wv1, wh2, wv2);
    kdw<<<1024, 288>>>();
    kaff2<<<1, 64>>>(gn, bn);
    kfinal<<<20736, 256>>>(x, out);
}